// round 2
// baseline (speedup 1.0000x reference)
#include <cuda_runtime.h>
#include <math.h>

// Problem constants
#define NPIX   120          // image side, detector count, t-samples
#define NANG   120          // angles
#define NK     61           // unique FFT bins (real input: |F[k]| = |F[120-k]|)
#define OFF    25           // zero-pad offset (px in [-24.65,143.65] -> +25 -> [0.35,168.65])
#define PW     170          // padded image rows/cols needed (0..169)
#define PSTR   171          // padded row stride (odd -> good bank spread)
#define NTHR   1024

#define SIMG_FLOATS  (PW * PSTR)            // 29070
#define SSINO_FLOATS (NANG * NPIX)          // 14400
// layout: simg | ssino | sang(float2 x128) | stw(float2 x128) | sout(64) | sred(64)
#define SANG_OFF  (SIMG_FLOATS + SSINO_FLOATS)
#define STW_OFF   (SANG_OFF + 256)
#define SOUT_OFF  (STW_OFF + 256)
#define SRED_OFF  (SOUT_OFF + 64)
#define SMEM_FLOATS (SRED_OFF + 64)
#define SMEM_BYTES  (SMEM_FLOATS * 4)

__global__ void __launch_bounds__(NTHR, 1)
ring_kernel(const float* __restrict__ bev, float* __restrict__ out)
{
    extern __shared__ float sm[];
    float*  simg  = sm;                        // padded image
    float*  ssino = sm + SIMG_FLOATS;          // sinogram [angle][s]
    float2* sang  = (float2*)(sm + SANG_OFF);  // (cos, sin) per angle
    float2* stw   = (float2*)(sm + STW_OFF);   // twiddle (cos, -sin)(2*pi*m/120)
    float*  sout  = sm + SOUT_OFF;             // 61 spectrum-sum bins
    float*  sred  = sm + SRED_OFF;             // reduction scratch + norm

    const int tid = threadIdx.x;
    const int b   = blockIdx.x;

    // ---- Phase 0: exact trig tables (double precision, once per CTA) ----
    if (tid < NANG) {
        double th = 6.283185307179586476925287 * (double)tid / 119.0;
        double s, c;
        sincos(th, &s, &c);
        sang[tid] = make_float2((float)c, (float)s);

        double ws, wc;
        sincospi((double)tid / 60.0, &ws, &wc);  // angle 2*pi*m/120
        stw[tid] = make_float2((float)wc, (float)(-ws));
    }
    if (tid < 64) sout[tid] = 0.0f;

    // ---- Phase 1: zero-padded image load ----
    for (int i = tid; i < SIMG_FLOATS; i += NTHR) simg[i] = 0.0f;
    __syncthreads();
    const float* g = bev + (long)b * (NPIX * NPIX);
    for (int i = tid; i < NPIX * NPIX; i += NTHR) {
        int r = i / NPIX;
        int c = i - r * NPIX;
        simg[(r + OFF) * PSTR + (c + OFF)] = g[i];
    }
    __syncthreads();

    // ---- Phase 2: Radon (no bounds checks thanks to padding) ----
    for (int p = tid; p < NANG * NPIX; p += NTHR) {
        int a  = p / NPIX;
        int si = p - a * NPIX;
        float2 cs = sang[a];
        float ct = cs.x, st = cs.y;
        float sv = (float)si - 59.5f;
        // px(t) = 84.5 + sv*ct + (59.5 - t)*st ; py(t) = 84.5 + sv*st + (t - 59.5)*ct
        float px0 = fmaf(sv, ct, fmaf(59.5f, st, 84.5f));
        float py0 = fmaf(sv, st, fmaf(-59.5f, ct, 84.5f));
        float acc = 0.0f;
        #pragma unroll 4
        for (int t = 0; t < NPIX; t++) {
            float tf = (float)t;
            float px = fmaf(tf, -st, px0);
            float py = fmaf(tf,  ct, py0);
            int xi = (int)px;                 // px >= 0 -> trunc == floor
            int yi = (int)py;
            float fx = px - (float)xi;
            float fy = py - (float)yi;
            const float* q = simg + yi * PSTR + xi;
            float v00 = q[0];
            float v01 = q[1];
            float v10 = q[PSTR];
            float v11 = q[PSTR + 1];
            float a0 = fmaf(fx, v01 - v00, v00);
            float b0 = fmaf(fx, v11 - v10, v10);
            acc += fmaf(fy, b0 - a0, a0);
        }
        ssino[p] = acc;  // p = a*120 + si
    }
    __syncthreads();

    // ---- Phase 3: real-input DFT magnitudes, k = 0..60, summed over angles ----
    // exact table twiddles: term n of bin k uses stw[(k*n) mod 120]
    for (int it = tid; it < NANG * NK; it += NTHR) {
        int a = it / NK;
        int k = it - a * NK;
        const float* v = ssino + a * NPIX;
        float re = 0.0f, im = 0.0f;
        int m = 0;
        #pragma unroll 8
        for (int n = 0; n < NPIX; n++) {
            float x = v[n];
            float2 w = stw[m];
            re = fmaf(x, w.x, re);
            im = fmaf(x, w.y, im);
            m += k;
            if (m >= NANG) m -= NANG;
        }
        // ortho norm: |F| = sqrt((re^2+im^2)/120 + 1e-15)
        float mag = sqrtf(fmaf(re, re, im * im) * (1.0f / 120.0f) + 1e-15f);
        atomicAdd(&sout[k], mag);
    }
    __syncthreads();

    // ---- Phase 4: L2 norm over full (mirrored) 120-vector, then write ----
    if (tid < NK) {
        float v = sout[tid];
        float w = (tid == 0 || tid == 60) ? 1.0f : 2.0f;  // mirrored bins count twice
        sred[tid] = w * v * v;
    }
    __syncthreads();
    if (tid == 0) {
        float s = 0.0f;
        for (int i = 0; i < NK; i++) s += sred[i];
        sred[63] = fmaxf(sqrtf(s), 1e-12f);
    }
    __syncthreads();
    float inv = 1.0f / sred[63];
    for (int k = tid; k < NPIX; k += NTHR) {
        int kk = (k <= 60) ? k : (NPIX - k);
        out[(long)b * NPIX + k] = sout[kk] * inv;
    }
}

extern "C" void kernel_launch(void* const* d_in, const int* in_sizes, int n_in,
                              void* d_out, int out_size)
{
    const float* bev = (const float*)d_in[0];
    float* out = (float*)d_out;
    int B = in_sizes[0] / (NPIX * NPIX);   // 1024

    cudaFuncSetAttribute(ring_kernel,
                         cudaFuncAttributeMaxDynamicSharedMemorySize, SMEM_BYTES);
    ring_kernel<<<B, NTHR, SMEM_BYTES>>>(bev, out);
}

// round 3
// speedup vs baseline: 1.2756x; 1.2756x over previous
#include <cuda_runtime.h>
#include <cuda_fp16.h>
#include <math.h>

// Problem constants
#define NPIX   120          // image side, detector count, t-samples
#define NANG   120          // angles
#define NK     61           // unique FFT bins (real input: |F[k]| = |F[120-k]|)
#define OFF    25           // zero-pad offset (px in [0.35,168.65])
#define PW     170          // padded image rows/cols (indices 0..169)
#define PSTR2  171          // packed row stride in half2 entries (odd -> bank spread)
#define NTHR   1024

#define PIMG_ENTRIES (PW * PSTR2)           // 29070 half2 (116280 B)
#define SSINO_FLOATS (NANG * NPIX)          // 14400 floats (57600 B)
// float-indexed layout after the packed image:
#define FBASE     (PIMG_ENTRIES)            // pimg entry == 1 float in size
#define SSINO_OFF (FBASE)
#define SANG_OFF  (SSINO_OFF + SSINO_FLOATS)
#define STW_OFF   (SANG_OFF + 256)
#define SOUT_OFF  (STW_OFF + 256)
#define SRED_OFF  (SOUT_OFF + 64)
#define SMEM_FLOATS (SRED_OFF + 64)
#define SMEM_BYTES  (SMEM_FLOATS * 4)

__global__ void __launch_bounds__(NTHR, 1)
ring_kernel(const float* __restrict__ bev, float* __restrict__ out)
{
    extern __shared__ float sm[];
    __half2* pimg = (__half2*)sm;              // packed (img[x], img[x+1]) taps
    float*  ssino = sm + SSINO_OFF;            // sinogram [angle][s]; temp raw image
    float2* sang  = (float2*)(sm + SANG_OFF);  // (cos, sin) per angle
    float2* stw   = (float2*)(sm + STW_OFF);   // twiddle (cos, -sin)(2*pi*m/120)
    float*  sout  = sm + SOUT_OFF;             // 61 spectrum-sum bins
    float*  sred  = sm + SRED_OFF;             // reduction scratch + norm

    const int tid = threadIdx.x;
    const int b   = blockIdx.x;

    // ---- Phase 0: exact trig tables (double precision, once per CTA) ----
    if (tid < NANG) {
        double th = 6.283185307179586476925287 * (double)tid / 119.0;
        double s, c;
        sincos(th, &s, &c);
        sang[tid] = make_float2((float)c, (float)s);

        double ws, wc;
        sincospi((double)tid / 60.0, &ws, &wc);  // angle 2*pi*m/120
        stw[tid] = make_float2((float)wc, (float)(-ws));
    }
    if (tid < 64) sout[tid] = 0.0f;

    // ---- Phase 1a: coalesced raw image load into ssino (temp), zero pimg ----
    const float* g = bev + (long)b * (NPIX * NPIX);
    for (int i = tid; i < NPIX * NPIX; i += NTHR) ssino[i] = g[i];
    for (int i = tid; i < PIMG_ENTRIES; i += NTHR) pimg[i] = __half2half2(__ushort_as_half(0));
    __syncthreads();

    // ---- Phase 1b: build packed half2 taps: pimg[r][c] = (img(r-25,c-25), img(r-25,c-24)) ----
    for (int i = tid; i < PW * PW; i += NTHR) {
        int r = i / PW;
        int c = i - r * PW;
        int y = r - OFF;
        int x = c - OFF;
        float v0 = 0.0f, v1 = 0.0f;
        if (y >= 0 && y < NPIX) {
            const float* row = ssino + y * NPIX;
            if (x >= 0 && x < NPIX)          v0 = row[x];
            if (x + 1 >= 0 && x + 1 < NPIX)  v1 = row[x + 1];
        }
        pimg[r * PSTR2 + c] = __floats2half2_rn(v0, v1);
    }
    __syncthreads();

    // ---- Phase 2: Radon, 2 x LDS.32 per bilinear sample ----
    for (int p = tid; p < NANG * NPIX; p += NTHR) {
        int a  = p / NPIX;
        int si = p - a * NPIX;
        float2 cs = sang[a];
        float ct = cs.x, st = cs.y;
        float sv = (float)si - 59.5f;
        // px(t) = 84.5 + sv*ct + (59.5 - t)*st ; py(t) = 84.5 + sv*st + (t - 59.5)*ct
        float px0 = fmaf(sv, ct, fmaf(59.5f, st, 84.5f));
        float py0 = fmaf(sv, st, fmaf(-59.5f, ct, 84.5f));
        float acc = 0.0f;
        #pragma unroll 4
        for (int t = 0; t < NPIX; t++) {
            float tf = (float)t;
            float px = fmaf(tf, -st, px0);
            float py = fmaf(tf,  ct, py0);
            int xi = (int)px;                 // px >= 0 -> trunc == floor
            int yi = (int)py;
            float fx = px - (float)xi;
            float fy = py - (float)yi;
            const __half2* q = pimg + yi * PSTR2 + xi;
            float2 top = __half22float2(q[0]);       // (v00, v01)
            float2 bot = __half22float2(q[PSTR2]);   // (v10, v11)
            float a0 = fmaf(fx, top.y - top.x, top.x);
            float b0 = fmaf(fx, bot.y - bot.x, bot.x);
            acc += fmaf(fy, b0 - a0, a0);
        }
        ssino[p] = acc;  // p = a*120 + si
    }
    __syncthreads();

    // ---- Phase 3: real-input DFT magnitudes, k = 0..60, summed over angles ----
    for (int it = tid; it < NANG * NK; it += NTHR) {
        int a = it / NK;
        int k = it - a * NK;
        const float* v = ssino + a * NPIX;
        float re = 0.0f, im = 0.0f;
        int m = 0;
        #pragma unroll 8
        for (int n = 0; n < NPIX; n++) {
            float x = v[n];
            float2 w = stw[m];
            re = fmaf(x, w.x, re);
            im = fmaf(x, w.y, im);
            m += k;
            if (m >= NANG) m -= NANG;
        }
        // ortho norm: |F| = sqrt((re^2+im^2)/120 + 1e-15)
        float mag = sqrtf(fmaf(re, re, im * im) * (1.0f / 120.0f) + 1e-15f);
        atomicAdd(&sout[k], mag);
    }
    __syncthreads();

    // ---- Phase 4: L2 norm over full (mirrored) 120-vector, then write ----
    if (tid < NK) {
        float v = sout[tid];
        float w = (tid == 0 || tid == 60) ? 1.0f : 2.0f;  // mirrored bins count twice
        sred[tid] = w * v * v;
    }
    __syncthreads();
    if (tid == 0) {
        float s = 0.0f;
        for (int i = 0; i < NK; i++) s += sred[i];
        sred[63] = fmaxf(sqrtf(s), 1e-12f);
    }
    __syncthreads();
    float inv = 1.0f / sred[63];
    for (int k = tid; k < NPIX; k += NTHR) {
        int kk = (k <= 60) ? k : (NPIX - k);
        out[(long)b * NPIX + k] = sout[kk] * inv;
    }
}

extern "C" void kernel_launch(void* const* d_in, const int* in_sizes, int n_in,
                              void* d_out, int out_size)
{
    const float* bev = (const float*)d_in[0];
    float* out = (float*)d_out;
    int B = in_sizes[0] / (NPIX * NPIX);   // 1024

    cudaFuncSetAttribute(ring_kernel,
                         cudaFuncAttributeMaxDynamicSharedMemorySize, SMEM_BYTES);
    ring_kernel<<<B, NTHR, SMEM_BYTES>>>(bev, out);
}

// round 4
// speedup vs baseline: 1.4650x; 1.1484x over previous
#include <cuda_runtime.h>
#include <cuda_fp16.h>
#include <math.h>

#define NPIX 120
#define NANG 120
#define NK   61
#define OFF  25
#define PW   170
#define PSTR 171          // texel row stride (u32 quads), odd
#define SSTR 121          // transposed sinogram stride [s][a], odd
#define NTHR 1024

#define PIMG_WORDS   (PW * PSTR)        // 29070 u32 fp8-quad texels
#define SSINO_FLOATS (NPIX * SSTR)      // 14520
#define SSINO_OFF (PIMG_WORDS)
#define SANG_OFF  (SSINO_OFF + SSINO_FLOATS)
#define STW_OFF   (SANG_OFF + 256)
#define SOUT_OFF  (STW_OFF + 256)
#define SRED_OFF  (SOUT_OFF + 64)
#define SMEM_FLOATS (SRED_OFF + 64)
#define SMEM_BYTES  (SMEM_FLOATS * 4)   // ~178 KB

typedef unsigned long long u64;

__device__ __forceinline__ u64 pk2(float lo, float hi) {
    u64 d; asm("mov.b64 %0,{%1,%2};" : "=l"(d) : "f"(lo), "f"(hi)); return d;
}
__device__ __forceinline__ u64 fma2(u64 a, u64 b, u64 c) {
    u64 d; asm("fma.rn.f32x2 %0,%1,%2,%3;" : "=l"(d) : "l"(a), "l"(b), "l"(c)); return d;
}
__device__ __forceinline__ u64 add2(u64 a, u64 b) {
    u64 d; asm("add.rn.f32x2 %0,%1,%2;" : "=l"(d) : "l"(a), "l"(b)); return d;
}

__global__ void __launch_bounds__(NTHR, 1)
ring_kernel(const float* __restrict__ bev, float* __restrict__ out)
{
    extern __shared__ float sm[];
    unsigned* pimg  = (unsigned*)sm;           // fp8-quad texels
    float*    ssino = sm + SSINO_OFF;          // transposed sinogram [s][a]; temp raw image
    float2*   sang  = (float2*)(sm + SANG_OFF);
    float2*   stw   = (float2*)(sm + STW_OFF);
    float*    sout  = sm + SOUT_OFF;
    float*    sred  = sm + SRED_OFF;

    const int tid = threadIdx.x;
    const int b   = blockIdx.x;

    unsigned pimg_base;
    {
        unsigned long long tmp;
        asm("cvta.to.shared.u64 %0, %1;" : "=l"(tmp) : "l"((void*)pimg));
        pimg_base = (unsigned)tmp;
    }
    // fold magic-bias correction into base: word = (iyb*171 + ixb) has bias 0x4B000000*172
    const unsigned pb = pimg_base - (unsigned)(0x4B000000u * 172u) * 4u;

    // ---- Phase 0: exact trig tables (double precision, once per CTA) ----
    if (tid < NANG) {
        double th = 6.283185307179586476925287 * (double)tid / 119.0;
        double s, c;
        sincos(th, &s, &c);
        sang[tid] = make_float2((float)c, (float)s);
        double ws, wc;
        sincospi((double)tid / 60.0, &ws, &wc);
        stw[tid] = make_float2((float)wc, (float)(-ws));
    }
    if (tid < 64) sout[tid] = 0.0f;

    // ---- Phase 1a: raw image into ssino temp (coalesced), zero texels ----
    const float* g = bev + (long)b * (NPIX * NPIX);
    for (int i = tid; i < NPIX * NPIX; i += NTHR) ssino[i] = g[i];
    for (int i = tid; i < PIMG_WORDS; i += NTHR) pimg[i] = 0u;
    __syncthreads();

    // ---- Phase 1b: build fp8-quad texels: (v00,v01,v10,v11) @ (y+25, x+25) ----
    for (int i = tid; i < PW * PW; i += NTHR) {
        int r = i / PW;
        int c = i - r * PW;
        int y = r - OFF;
        int x = c - OFF;
        float v00 = 0.f, v01 = 0.f, v10 = 0.f, v11 = 0.f;
        bool xok0 = (x >= 0 && x < NPIX);
        bool xok1 = (x + 1 >= 0 && x + 1 < NPIX);
        if (y >= 0 && y < NPIX) {
            const float* row = ssino + y * NPIX;
            if (xok0) v00 = row[x];
            if (xok1) v01 = row[x + 1];
        }
        if (y + 1 >= 0 && y + 1 < NPIX) {
            const float* row = ssino + (y + 1) * NPIX;
            if (xok0) v10 = row[x];
            if (xok1) v11 = row[x + 1];
        }
        unsigned short lo, hi;
        asm("cvt.rn.satfinite.e4m3x2.f32 %0, %1, %2;" : "=h"(lo) : "f"(v01), "f"(v00));
        asm("cvt.rn.satfinite.e4m3x2.f32 %0, %1, %2;" : "=h"(hi) : "f"(v11), "f"(v10));
        pimg[r * PSTR + c] = (unsigned)lo | ((unsigned)hi << 16);
    }
    __syncthreads();

    // ---- Phase 2: Radon. 1 LDS.32 per bilinear sample, f32x2 coords, half2 lerp ----
    const u64 ONE2 = 0x3F8000003F800000ull;                  // (1,1)
    const u64 C1   = pk2(8388607.5f, 8388607.5f);            // 2^23 - 0.5 (round->floor)
    const u64 C2n  = pk2(-8388608.0f, -8388608.0f);          // -2^23
    const u64 M1   = pk2(-1.0f, -1.0f);
    for (int p = tid; p < NANG * NPIX; p += NTHR) {
        int a  = p / NPIX;
        int si = p - a * NPIX;
        float2 cs = sang[a];
        float ct = cs.x, st = cs.y;
        float sv = (float)si - 59.5f;
        float px0 = fmaf(sv, ct, fmaf(59.5f, st, 84.5f));
        float py0 = fmaf(sv, st, fmaf(-59.5f, ct, 84.5f));
        u64 P0 = pk2(px0, py0);
        u64 D  = pk2(-st, ct);
        u64 T  = 0ull;                                        // (0.0, 0.0)
        float acc = 0.0f;
        #pragma unroll 8
        for (int t = 0; t < NPIX; t++) {
            u64 P  = fma2(T, D, P0);
            T = add2(T, ONE2);                                // exact integer steps
            u64 PM = add2(P, C1);                             // round(p-0.5)+2^23
            u64 XI = add2(PM, C2n);                           // (floor-ish xf, yf)
            u64 FR = fma2(XI, M1, P);                         // (fx, fy), exact subs
            unsigned ixb, iyb;
            asm("mov.b64 {%0,%1},%2;" : "=r"(ixb), "=r"(iyb) : "l"(PM));
            float fx, fy;
            asm("mov.b64 {%0,%1},%2;" : "=f"(fx), "=f"(fy) : "l"(FR));
            unsigned addr = pb + (iyb * 171u + ixb) * 4u;
            unsigned quad;
            asm("ld.shared.b32 %0,[%1];" : "=r"(quad) : "r"(addr));
            unsigned topu, botu;
            asm("cvt.rn.f16x2.e4m3x2 %0, %1;" : "=r"(topu) : "h"((unsigned short)quad));
            asm("cvt.rn.f16x2.e4m3x2 %0, %1;" : "=r"(botu) : "h"((unsigned short)(quad >> 16)));
            __half2 top = *(__half2*)&topu;                   // (v00, v01)
            __half2 bot = *(__half2*)&botu;                   // (v10, v11)
            unsigned fxyu;
            asm("cvt.rn.f16x2.f32 %0, %1, %2;" : "=r"(fxyu) : "f"(fy), "f"(fx)); // hi=fy, lo=fx
            __half2 fxy = *(__half2*)&fxyu;
            __half2 dv  = __hsub2(bot, top);
            __half2 fy2 = __half2half2(__high2half(fxy));
            __half2 m   = __hfma2(dv, fy2, top);              // y-lerp
            __half dm   = __hsub(__high2half(m), __low2half(m));
            __half rr   = __hfma(dm, __low2half(fxy), __low2half(m)); // x-lerp
            acc += __half2float(rr);
        }
        ssino[si * SSTR + a] = acc;   // transposed store, stride 121 (conflict-free)
    }
    __syncthreads();

    // ---- Phase 3: DFT, lanes share k (twiddle broadcast), v reads stride-1 ----
    for (int it = tid; it < NK * NANG; it += NTHR) {
        int k = it / NANG;
        int a = it - k * NANG;
        const float* v = ssino + a;
        float re = 0.0f, im = 0.0f;
        int m = 0;
        #pragma unroll 8
        for (int n = 0; n < NPIX; n++) {
            float x = v[n * SSTR];
            float2 w = stw[m];
            re = fmaf(x, w.x, re);
            im = fmaf(x, w.y, im);
            m += k;
            if (m >= NANG) m -= NANG;
        }
        float mag = sqrtf(fmaf(re, re, im * im) * (1.0f / 120.0f) + 1e-15f);
        atomicAdd(&sout[k], mag);
    }
    __syncthreads();

    // ---- Phase 4: L2 norm over mirrored 120-vector, write ----
    if (tid < NK) {
        float v = sout[tid];
        float w = (tid == 0 || tid == 60) ? 1.0f : 2.0f;
        sred[tid] = w * v * v;
    }
    __syncthreads();
    if (tid == 0) {
        float s = 0.0f;
        for (int i = 0; i < NK; i++) s += sred[i];
        sred[63] = fmaxf(sqrtf(s), 1e-12f);
    }
    __syncthreads();
    float inv = 1.0f / sred[63];
    for (int k = tid; k < NPIX; k += NTHR) {
        int kk = (k <= 60) ? k : (NPIX - k);
        out[(long)b * NPIX + k] = sout[kk] * inv;
    }
}

extern "C" void kernel_launch(void* const* d_in, const int* in_sizes, int n_in,
                              void* d_out, int out_size)
{
    const float* bev = (const float*)d_in[0];
    float* out = (float*)d_out;
    int B = in_sizes[0] / (NPIX * NPIX);   // 1024

    cudaFuncSetAttribute(ring_kernel,
                         cudaFuncAttributeMaxDynamicSharedMemorySize, SMEM_BYTES);
    ring_kernel<<<B, NTHR, SMEM_BYTES>>>(bev, out);
}

// round 5
// speedup vs baseline: 1.5736x; 1.0742x over previous
#include <cuda_runtime.h>
#include <cuda_fp16.h>
#include <math.h>

#define NPIX 120
#define NANG 120
#define NK   61
#define OFF  25
#define PW   170
#define PSTR 171          // texel row stride (u32 quads), odd
#define SSTR 121          // transposed sinogram stride [s][a], odd
#define NTHR 1024

#define PIMG_WORDS   (PW * PSTR)        // 29070 u32 fp8-quad texels
#define SSINO_FLOATS (NPIX * SSTR)      // 14520
#define SSINO_OFF (PIMG_WORDS)
#define SANG_OFF  (SSINO_OFF + SSINO_FLOATS)
#define STW_OFF   (SANG_OFF + 256)
#define SOUT_OFF  (STW_OFF + 256)
#define SRED_OFF  (SOUT_OFF + 64)
#define SMEM_FLOATS (SRED_OFF + 64)
#define SMEM_BYTES  (SMEM_FLOATS * 4)   // ~178 KB

typedef unsigned long long u64;

__device__ __forceinline__ u64 pk2(float lo, float hi) {
    u64 d; asm("mov.b64 %0,{%1,%2};" : "=l"(d) : "f"(lo), "f"(hi)); return d;
}
__device__ __forceinline__ u64 fma2(u64 a, u64 b, u64 c) {
    u64 d; asm("fma.rn.f32x2 %0,%1,%2,%3;" : "=l"(d) : "l"(a), "l"(b), "l"(c)); return d;
}
__device__ __forceinline__ u64 add2(u64 a, u64 b) {
    u64 d; asm("add.rn.f32x2 %0,%1,%2;" : "=l"(d) : "l"(a), "l"(b)); return d;
}

__global__ void __launch_bounds__(NTHR, 1)
ring_kernel(const float* __restrict__ bev, float* __restrict__ out)
{
    extern __shared__ float sm[];
    unsigned* pimg  = (unsigned*)sm;           // fp8-quad texels
    float*    ssino = sm + SSINO_OFF;          // transposed sinogram [s][a]; temp raw image
    float2*   sang  = (float2*)(sm + SANG_OFF);
    float2*   stw   = (float2*)(sm + STW_OFF);
    float*    sout  = sm + SOUT_OFF;
    float*    sred  = sm + SRED_OFF;

    const int tid = threadIdx.x;
    const int b   = blockIdx.x;

    unsigned pimg_base;
    {
        unsigned long long tmp;
        asm("cvta.to.shared.u64 %0, %1;" : "=l"(tmp) : "l"((void*)pimg));
        pimg_base = (unsigned)tmp;
    }
    // fold magic-bias correction into base: word index (iyb*171 + ixb) carries bias 0x4B000000*172
    const unsigned pb = pimg_base - (unsigned)(0x4B000000u * 172u) * 4u;

    // ---- Phase 0: exact trig tables (double precision, once per CTA) ----
    if (tid < NANG) {
        double th = 6.283185307179586476925287 * (double)tid / 119.0;
        double s, c;
        sincos(th, &s, &c);
        sang[tid] = make_float2((float)c, (float)s);
        double ws, wc;
        sincospi((double)tid / 60.0, &ws, &wc);
        stw[tid] = make_float2((float)wc, (float)(-ws));
    }
    if (tid < 64) sout[tid] = 0.0f;

    // ---- Phase 1a: raw image into ssino temp (coalesced), zero texels ----
    const float* g = bev + (long)b * (NPIX * NPIX);
    for (int i = tid; i < NPIX * NPIX; i += NTHR) ssino[i] = g[i];
    for (int i = tid; i < PIMG_WORDS; i += NTHR) pimg[i] = 0u;
    __syncthreads();

    // ---- Phase 1b: build fp8-quad texels: (v00,v01,v10,v11) @ (y+25, x+25) ----
    for (int i = tid; i < PW * PW; i += NTHR) {
        int r = i / PW;
        int c = i - r * PW;
        int y = r - OFF;
        int x = c - OFF;
        float v00 = 0.f, v01 = 0.f, v10 = 0.f, v11 = 0.f;
        bool xok0 = (x >= 0 && x < NPIX);
        bool xok1 = (x + 1 >= 0 && x + 1 < NPIX);
        if (y >= 0 && y < NPIX) {
            const float* row = ssino + y * NPIX;
            if (xok0) v00 = row[x];
            if (xok1) v01 = row[x + 1];
        }
        if (y + 1 >= 0 && y + 1 < NPIX) {
            const float* row = ssino + (y + 1) * NPIX;
            if (xok0) v10 = row[x];
            if (xok1) v11 = row[x + 1];
        }
        unsigned short lo, hi;
        asm("cvt.rn.satfinite.e4m3x2.f32 %0, %1, %2;" : "=h"(lo) : "f"(v01), "f"(v00));
        asm("cvt.rn.satfinite.e4m3x2.f32 %0, %1, %2;" : "=h"(hi) : "f"(v11), "f"(v10));
        pimg[r * PSTR + c] = (unsigned)lo | ((unsigned)hi << 16);
    }
    __syncthreads();

    // ---- Phase 2: clipped Radon. 1 LDS.32/sample, f32x2 coords, half2 lerp ----
    const u64 C1   = pk2(8388607.5f, 8388607.5f);            // 2^23 - 0.5 (round->floor)
    const u64 C2n  = pk2(-8388608.0f, -8388608.0f);          // -2^23
    const u64 M1   = pk2(-1.0f, -1.0f);
    for (int p = tid; p < NANG * NPIX; p += NTHR) {
        int a  = p / NPIX;
        int si = p - a * NPIX;
        float2 cs = sang[a];
        float ct = cs.x, st = cs.y;
        float sv = (float)si - 59.5f;
        float px0 = fmaf(sv, ct, fmaf(59.5f, st, 84.5f));
        float py0 = fmaf(sv, st, fmaf(-59.5f, ct, 84.5f));
        float dx = -st, dy = ct;

        // clip to texel-nonzero region: px,py in (23.5, 145.5) (widened, safe)
        float t0 = 0.0f, t1 = 119.0f;
        if (fabsf(dx) > 1e-9f) {
            float inv = __fdividef(1.0f, dx);
            float A = (23.5f - px0) * inv, B = (145.5f - px0) * inv;
            t0 = fmaxf(t0, fminf(A, B));
            t1 = fminf(t1, fmaxf(A, B));
        } else if (px0 < 23.5f || px0 > 145.5f) t1 = -2.0f;
        if (fabsf(dy) > 1e-9f) {
            float inv = __fdividef(1.0f, dy);
            float A = (23.5f - py0) * inv, B = (145.5f - py0) * inv;
            t0 = fmaxf(t0, fminf(A, B));
            t1 = fminf(t1, fmaxf(A, B));
        } else if (py0 < 23.5f || py0 > 145.5f) t1 = -2.0f;
        int ta = max(0, (int)t0 - 1);
        int tb = min(119, (int)t1 + 2);

        float acc = 0.0f;
        u64 D = pk2(dx, dy);
        u64 P = fma2(pk2((float)ta, (float)ta), D, pk2(px0, py0));
        #pragma unroll 4
        for (int t = ta; t <= tb; t++) {
            u64 PM = add2(P, C1);                             // round(p-0.5)+2^23
            u64 XI = add2(PM, C2n);                           // (xf, yf) floor as floats
            u64 FR = fma2(XI, M1, P);                         // (fx, fy)
            unsigned ixb, iyb;
            asm("mov.b64 {%0,%1},%2;" : "=r"(ixb), "=r"(iyb) : "l"(PM));
            float fx, fy;
            asm("mov.b64 {%0,%1},%2;" : "=f"(fx), "=f"(fy) : "l"(FR));
            P = add2(P, D);                                   // sequential step (drift ~2e-3 px, negligible)
            unsigned addr = pb + (iyb * 171u + ixb) * 4u;
            unsigned quad;
            asm("ld.shared.b32 %0,[%1];" : "=r"(quad) : "r"(addr));
            unsigned topu, botu;
            asm("cvt.rn.f16x2.e4m3x2 %0, %1;" : "=r"(topu) : "h"((unsigned short)quad));
            asm("cvt.rn.f16x2.e4m3x2 %0, %1;" : "=r"(botu) : "h"((unsigned short)(quad >> 16)));
            __half2 top = *(__half2*)&topu;                   // (v00, v01)
            __half2 bot = *(__half2*)&botu;                   // (v10, v11)
            unsigned fxyu;
            asm("cvt.rn.f16x2.f32 %0, %1, %2;" : "=r"(fxyu) : "f"(fy), "f"(fx)); // hi=fy, lo=fx
            __half2 fxy = *(__half2*)&fxyu;
            __half2 dv  = __hsub2(bot, top);
            __half2 fy2 = __half2half2(__high2half(fxy));
            __half2 m   = __hfma2(dv, fy2, top);              // y-lerp
            __half dm   = __hsub(__high2half(m), __low2half(m));
            __half rr   = __hfma(dm, __low2half(fxy), __low2half(m)); // x-lerp
            acc += __half2float(rr);
        }
        ssino[si * SSTR + a] = acc;   // transposed store, stride 121 (conflict-free)
    }
    __syncthreads();

    // ---- Phase 3a: fold sinogram about n=60: rows n := x[n]+x[120-n], rows 120-n := x[n]-x[120-n] ----
    for (int it = tid; it < 59 * NANG; it += NTHR) {
        int n = 1 + it / NANG;
        int a = it - (n - 1) * NANG;
        float xa = ssino[n * SSTR + a];
        float xb = ssino[(NPIX - n) * SSTR + a];
        ssino[n * SSTR + a]          = xa + xb;   // xs
        ssino[(NPIX - n) * SSTR + a] = xa - xb;   // xd
    }
    __syncthreads();

    // ---- Phase 3b: folded real DFT, k = 0..60; lanes share k (twiddle broadcast) ----
    for (int it = tid; it < NK * NANG; it += NTHR) {
        int k = it / NANG;
        int a = it - k * NANG;
        const float* v = ssino + a;
        float x0  = v[0];
        float x60 = v[60 * SSTR];
        float re = (k & 1) ? (x0 - x60) : (x0 + x60);
        float im = 0.0f;
        int m = k;
        #pragma unroll 8
        for (int n = 1; n <= 59; n++) {
            float xs = v[n * SSTR];
            float xd = v[(NPIX - n) * SSTR];
            float2 w = stw[m];
            re = fmaf(xs, w.x, re);
            im = fmaf(xd, w.y, im);
            m += k;
            if (m >= NANG) m -= NANG;
        }
        float mag = sqrtf(fmaf(re, re, im * im) * (1.0f / 120.0f) + 1e-15f);
        atomicAdd(&sout[k], mag);
    }
    __syncthreads();

    // ---- Phase 4: L2 norm over mirrored 120-vector, write ----
    if (tid < NK) {
        float v = sout[tid];
        float w = (tid == 0 || tid == 60) ? 1.0f : 2.0f;
        sred[tid] = w * v * v;
    }
    __syncthreads();
    if (tid == 0) {
        float s = 0.0f;
        for (int i = 0; i < NK; i++) s += sred[i];
        sred[63] = fmaxf(sqrtf(s), 1e-12f);
    }
    __syncthreads();
    float inv = 1.0f / sred[63];
    for (int k = tid; k < NPIX; k += NTHR) {
        int kk = (k <= 60) ? k : (NPIX - k);
        out[(long)b * NPIX + k] = sout[kk] * inv;
    }
}

extern "C" void kernel_launch(void* const* d_in, const int* in_sizes, int n_in,
                              void* d_out, int out_size)
{
    const float* bev = (const float*)d_in[0];
    float* out = (float*)d_out;
    int B = in_sizes[0] / (NPIX * NPIX);   // 1024

    cudaFuncSetAttribute(ring_kernel,
                         cudaFuncAttributeMaxDynamicSharedMemorySize, SMEM_BYTES);
    ring_kernel<<<B, NTHR, SMEM_BYTES>>>(bev, out);
}